// round 10
// baseline (speedup 1.0000x reference)
#include <cuda_runtime.h>

#define THETA 0.5f
#define CS 128           // rows per chunk (per block)
#define NG 4             // row subgroups per block
#define RG 32            // rows per subgroup
#define PF 4             // prefetch depth in float4 rows
// header floats: s_c[CS]+s_r[CS]+s_w[CS]+s_Tg[NG] = 388 -> pad to 392 (16B aligned)
#define SM_HDR 392

// Scratch: per-chunk local + inclusive endpoints and states.
__device__ float g_Lc[1 << 20];   // B*chunks*D floats max (64*32*256 = 524288)
__device__ float g_Ic[1 << 20];
__device__ int   g_state[8192];   // 0=none, 1=local, 2=inclusive

__global__ void init_flags_kernel(int n) {
    int i = blockIdx.x * blockDim.x + threadIdx.x;
    if (i < n) g_state[i] = 0;
}

__device__ __forceinline__ void fma4(float4& a, float w, const float4& v) {
    a.x = fmaf(w, v.x, a.x); a.y = fmaf(w, v.y, a.y);
    a.z = fmaf(w, v.z, a.z); a.w = fmaf(w, v.w, a.w);
}

__global__ __launch_bounds__(256, 4)
void ou_scan_kernel(const float* __restrict__ t,
                    const float* __restrict__ x0,
                    const float* __restrict__ z,
                    float* __restrict__ out,
                    int B, int S, int D, int chunks)
{
    extern __shared__ __align__(16) float sm[];
    float*  s_c  = sm;                  // [CS] per-row decay
    float*  s_r  = sm + CS;             // [CS] per-row noise scale
    float*  s_w  = sm + 2 * CS;         // [CS] phase-1 weight: r * exp(-th*(Tg_end - t))
    float*  s_Tg = sm + 3 * CS;         // [NG] subgroup end-times
    float4* s_P  = (float4*)(sm + SM_HDR);   // [NG * 64] subgroup partials

    const int b  = blockIdx.x / chunks;
    const int k  = blockIdx.x % chunks;
    const int s0 = k * CS;
    const int rows = min(CS, S - s0);
    const bool full = (rows == CS);
    const int tid = threadIdx.x;
    const int g  = tid >> 6;            // subgroup 0..3
    const int l  = tid & 63;            // float4 lane (d = 4*l)

    const float* tb = t + (size_t)b * S;
    const float Tprev = (k == 0) ? 0.0f : tb[s0 - 1];

    // ---- phase 0: per-row constants ----
    for (int i = tid; i < rows; i += 256) {
        float tc = tb[s0 + i];
        float tp = (s0 + i == 0) ? 0.0f : tb[s0 + i - 1];
        float c  = __expf(-THETA * (tc - tp));
        float r  = sqrtf(fmaxf(1.0f - c * c, 0.0f));
        s_c[i] = c;
        s_r[i] = r;
        const int gi = i / RG;
        float Tge = tb[min(s0 + (gi + 1) * RG - 1, S - 1)];
        s_w[i] = r * __expf(-THETA * (Tge - tc));
    }
    if (tid < NG) s_Tg[tid] = tb[min(s0 + (tid + 1) * RG - 1, S - 1)];
    __syncthreads();

    // ---- phase 1: subgroup partial = weighted sum (order-free!) read in REVERSE ----
    const int r0 = g * RG;
    const float4* zb4 = (const float4*)(z + ((size_t)b * S + s0 + r0) * D) + l;
    const int strd = D >> 2;            // float4 per row

    float4 acc0 = make_float4(0.f, 0.f, 0.f, 0.f);
    float4 acc1 = make_float4(0.f, 0.f, 0.f, 0.f);
    if (full) {
        float4 cur[PF], nxt[PF];
        #pragma unroll
        for (int u = 0; u < PF; ++u)
            cur[u] = __ldcg(zb4 + (size_t)(RG - 1 - u) * strd);
        for (int s = 0; s < RG; s += PF) {
            if (s + 2 * PF <= RG) {
                #pragma unroll
                for (int u = 0; u < PF; ++u)
                    nxt[u] = __ldcg(zb4 + (size_t)(RG - 1 - (s + PF + u)) * strd);
            }
            #pragma unroll
            for (int u = 0; u < PF; ++u) {
                const float w = s_w[r0 + RG - 1 - (s + u)];
                if (u & 1) fma4(acc1, w, cur[u]); else fma4(acc0, w, cur[u]);
            }
            #pragma unroll
            for (int u = 0; u < PF; ++u) cur[u] = nxt[u];
        }
    } else {
        const int gr = max(0, min(RG, rows - r0));
        for (int s = 0; s < gr; ++s) {
            const float4 zv = __ldcg(zb4 + (size_t)s * strd);
            fma4(acc0, s_w[r0 + s], zv);
        }
    }
    acc0.x += acc1.x; acc0.y += acc1.y; acc0.z += acc1.z; acc0.w += acc1.w;
    float4 x0v = make_float4(0.f, 0.f, 0.f, 0.f);
    if (k == 0) {
        x0v = ((const float4*)(x0 + (size_t)b * D))[l];
        if (g == 0)   // x0 contribution to subgroup-0 partial (Tprev = 0)
            fma4(acc0, __expf(-THETA * s_Tg[0]), x0v);
    }
    s_P[g * 64 + l] = acc0;
    __syncthreads();

    // ---- block local endpoint (every thread, for its lane l) ----
    const float Tend = s_Tg[NG - 1];
    float4 Lb = make_float4(0.f, 0.f, 0.f, 0.f);
    #pragma unroll
    for (int gp = 0; gp < NG; ++gp)
        fma4(Lb, __expf(-THETA * (Tend - s_Tg[gp])), s_P[gp * 64 + l]);

    // ---- publish LOCAL (state 1) ----
    const int base = b * chunks;
    const int cid  = base + k;
    if (g == 0) ((float4*)g_Lc)[(size_t)cid * 64 + l] = Lb;
    __threadfence();
    __syncthreads();
    if (tid == 0) {
        asm volatile("st.release.gpu.global.b32 [%0], %1;"
                     :: "l"(&g_state[cid]), "r"(1) : "memory");
    }

    // ---- prefetch first PF rows for phase 3 (independent of the carry) ----
    float4 p3[PF];
    if (full) {
        #pragma unroll
        for (int u = 0; u < PF; ++u) p3[u] = __ldcs(zb4 + (size_t)u * strd);
    }

    // ---- phase 2: decoupled lookback walk (usually 1-2 steps) ----
    float4 carry = make_float4(0.f, 0.f, 0.f, 0.f);
    if (k > 0) {
        int j = k - 1;
        for (;;) {
            int st;
            do {
                asm volatile("ld.acquire.gpu.global.b32 %0, [%1];"
                             : "=r"(st) : "l"(&g_state[base + j]) : "memory");
                if (!st) __nanosleep(32);
            } while (!st);
            const float Tj = tb[(j + 1) * CS - 1];
            const float w  = __expf(-THETA * (Tprev - Tj));
            const float4* src = (st == 2) ? (const float4*)g_Ic : (const float4*)g_Lc;
            fma4(carry, w, src[(size_t)(base + j) * 64 + l]);
            if (st == 2 || j == 0) break;   // chunk 0 local == inclusive
            --j;
        }
    }

    // ---- publish INCLUSIVE (state 2) ----
    if (k < chunks - 1) {   // last chunk has no successors
        if (g == 0) {
            float4 Iv = Lb;
            fma4(Iv, __expf(-THETA * (Tend - Tprev)), carry);
            ((float4*)g_Ic)[(size_t)cid * 64 + l] = Iv;
        }
        __threadfence();
        __syncthreads();
        if (tid == 0) {
            asm volatile("st.release.gpu.global.b32 [%0], %1;"
                         :: "l"(&g_state[cid]), "r"(2) : "memory");
        }
    }

    // ---- state entering THIS thread's subgroup ----
    const float Tgprev = (g == 0) ? Tprev : s_Tg[g - 1];
    float4 e = make_float4(0.f, 0.f, 0.f, 0.f);
    fma4(e, __expf(-THETA * (Tgprev - Tprev)), carry);
    for (int gp = 0; gp < g; ++gp)
        fma4(e, __expf(-THETA * (Tgprev - s_Tg[gp])), s_P[gp * 64 + l]);
    if (k == 0 && g == 0) {
        e.x += x0v.x; e.y += x0v.y; e.z += x0v.z; e.w += x0v.w;
    }

    // ---- phase 3: re-read z (L2-resident), forward recurrence with true carry ----
    float4* ob4 = (float4*)(out + ((size_t)b * S + s0 + r0) * D) + l;
    float4 y = e;
    if (full) {
        float4 cur[PF], nxt[PF];
        #pragma unroll
        for (int u = 0; u < PF; ++u) cur[u] = p3[u];
        for (int s = 0; s < RG; s += PF) {
            if (s + 2 * PF <= RG) {
                #pragma unroll
                for (int u = 0; u < PF; ++u)
                    nxt[u] = __ldcs(zb4 + (size_t)(s + PF + u) * strd);
            }
            #pragma unroll
            for (int u = 0; u < PF; ++u) {
                const float c = s_c[r0 + s + u];
                const float r = s_r[r0 + s + u];
                y.x = fmaf(c, y.x, r * cur[u].x);
                y.y = fmaf(c, y.y, r * cur[u].y);
                y.z = fmaf(c, y.z, r * cur[u].z);
                y.w = fmaf(c, y.w, r * cur[u].w);
                __stcs(ob4 + (size_t)(s + u) * strd, y);
            }
            #pragma unroll
            for (int u = 0; u < PF; ++u) cur[u] = nxt[u];
        }
    } else {
        const int gr = max(0, min(RG, rows - r0));
        for (int s = 0; s < gr; ++s) {
            const float4 zv = __ldcs(zb4 + (size_t)s * strd);
            const float c = s_c[r0 + s], r = s_r[r0 + s];
            y.x = fmaf(c, y.x, r * zv.x);
            y.y = fmaf(c, y.y, r * zv.y);
            y.z = fmaf(c, y.z, r * zv.z);
            y.w = fmaf(c, y.w, r * zv.w);
            __stcs(ob4 + (size_t)s * strd, y);
        }
    }
}

extern "C" void kernel_launch(void* const* d_in, const int* in_sizes, int n_in,
                              void* d_out, int out_size)
{
    const float* t  = (const float*)d_in[0];   // [B,S,1]
    const float* x0 = (const float*)d_in[1];   // [B,1,D]
    const float* z  = (const float*)d_in[2];   // [B,S,D]
    float* out = (float*)d_out;                // [B,S,D]

    const long n_t  = in_sizes[0];
    const long n_x0 = in_sizes[1];
    const long n_z  = in_sizes[2];
    const int D = (int)(n_z / n_t);
    const int B = (int)(n_x0 / D);
    const int S = (int)(n_t / B);
    const int chunks = (S + CS - 1) / CS;

    const int nflags = B * chunks;
    init_flags_kernel<<<(nflags + 255) / 256, 256>>>(nflags);

    const size_t smem = SM_HDR * sizeof(float) + (size_t)(NG * 64) * sizeof(float4);
    cudaFuncSetAttribute(ou_scan_kernel,
                         cudaFuncAttributeMaxDynamicSharedMemorySize, (int)smem);
    ou_scan_kernel<<<B * chunks, 256, smem>>>(t, x0, z, out, B, S, D, chunks);
}

// round 13
// speedup vs baseline: 1.1807x; 1.1807x over previous
#include <cuda_runtime.h>

#define THETA 0.5f
#define CS 256           // rows per chunk (per block)
#define NG 4             // row subgroups per block
#define RG 64            // rows per subgroup
#define PF 4             // prefetch depth in float4 rows
// header floats: s_c[CS]+s_r[CS]+s_w[CS]+s_T[64]+s_Tg[NG] = 3*256+64+4 = 836 -> pad 840
#define SM_HDR 840

// Scratch: per-chunk local endpoints + ready flags.
__device__ float g_L[1 << 20];   // B*chunks*D = 64*16*256 = 262144 floats max
__device__ int   g_flag[16384];

__global__ void init_flags_kernel(int n) {
    int i = blockIdx.x * blockDim.x + threadIdx.x;
    if (i < n) g_flag[i] = 0;
}

__device__ __forceinline__ void fma4(float4& a, float w, const float4& v) {
    a.x = fmaf(w, v.x, a.x); a.y = fmaf(w, v.y, a.y);
    a.z = fmaf(w, v.z, a.z); a.w = fmaf(w, v.w, a.w);
}

__global__ __launch_bounds__(256, 4)
void ou_scan_kernel(const float* __restrict__ t,
                    const float* __restrict__ x0,
                    const float* __restrict__ z,
                    float* __restrict__ out,
                    int B, int S, int D, int chunks)
{
    extern __shared__ __align__(16) float sm[];
    float*  s_c  = sm;                  // [CS] per-row decay
    float*  s_r  = sm + CS;             // [CS] per-row noise scale
    float*  s_w  = sm + 2 * CS;         // [CS] phase-1 weight r*exp(-th*(Tg_end-t))
    float*  s_T  = sm + 3 * CS;         // [64] predecessor chunk end-times
    float*  s_Tg = sm + 3 * CS + 64;    // [NG] subgroup end-times
    float4* s_P  = (float4*)(sm + SM_HDR);   // [NG * 64] subgroup partials

    const int b  = blockIdx.x / chunks;
    const int k  = blockIdx.x % chunks;
    const int s0 = k * CS;
    const int rows = min(CS, S - s0);
    const bool full = (rows == CS);
    const int tid = threadIdx.x;
    const int g  = tid >> 6;            // subgroup 0..3
    const int l  = tid & 63;            // float4 lane (d = 4*l)

    const float* tb = t + (size_t)b * S;
    const float Tprev = (k == 0) ? 0.0f : tb[s0 - 1];

    // ---- phase 0: per-row constants ----
    for (int i = tid; i < rows; i += 256) {
        float tc = tb[s0 + i];
        float tp = (s0 + i == 0) ? 0.0f : tb[s0 + i - 1];
        float c  = __expf(-THETA * (tc - tp));
        float r  = sqrtf(fmaxf(1.0f - c * c, 0.0f));
        s_c[i] = c;
        s_r[i] = r;
        const int gi = i / RG;
        float Tge = tb[min(s0 + (gi + 1) * RG - 1, S - 1)];
        s_w[i] = r * __expf(-THETA * (Tge - tc));
    }
    if (tid < NG) s_Tg[tid] = tb[min(s0 + (tid + 1) * RG - 1, S - 1)];
    __syncthreads();

    // ---- phase 1: subgroup partial = order-free weighted sum, read in REVERSE ----
    const int r0 = g * RG;
    const float4* zb4 = (const float4*)(z + ((size_t)b * S + s0 + r0) * D) + l;
    const int strd = D >> 2;            // float4 per row

    float4 acc0 = make_float4(0.f, 0.f, 0.f, 0.f);
    float4 acc1 = make_float4(0.f, 0.f, 0.f, 0.f);
    if (full) {
        float4 cur[PF], nxt[PF];
        #pragma unroll
        for (int u = 0; u < PF; ++u)
            cur[u] = __ldcg(zb4 + (size_t)(RG - 1 - u) * strd);
        for (int s = 0; s < RG; s += PF) {
            if (s + 2 * PF <= RG) {
                #pragma unroll
                for (int u = 0; u < PF; ++u)
                    nxt[u] = __ldcg(zb4 + (size_t)(RG - 1 - (s + PF + u)) * strd);
            }
            #pragma unroll
            for (int u = 0; u < PF; ++u) {
                const float w = s_w[r0 + RG - 1 - (s + u)];
                if (u & 1) fma4(acc1, w, cur[u]); else fma4(acc0, w, cur[u]);
            }
            #pragma unroll
            for (int u = 0; u < PF; ++u) cur[u] = nxt[u];
        }
    } else {
        const int gr = max(0, min(RG, rows - r0));
        for (int s = 0; s < gr; ++s) {
            const float4 zv = __ldcg(zb4 + (size_t)s * strd);
            fma4(acc0, s_w[r0 + s], zv);
        }
    }
    acc0.x += acc1.x; acc0.y += acc1.y; acc0.z += acc1.z; acc0.w += acc1.w;
    float4 x0v = make_float4(0.f, 0.f, 0.f, 0.f);
    if (k == 0) {
        x0v = ((const float4*)(x0 + (size_t)b * D))[l];
        if (g == 0)   // x0 contribution to subgroup-0 partial (state before chunk 0 at time 0)
            fma4(acc0, __expf(-THETA * s_Tg[0]), x0v);
    }
    s_P[g * 64 + l] = acc0;
    __syncthreads();

    // ---- block local endpoint (every thread, its lane l) ----
    const float Tend = s_Tg[NG - 1];
    float4 Lb = make_float4(0.f, 0.f, 0.f, 0.f);
    #pragma unroll
    for (int gp = 0; gp < NG; ++gp)
        fma4(Lb, __expf(-THETA * (Tend - s_Tg[gp])), s_P[gp * 64 + l]);

    // ---- publish local endpoint, then release flag ----
    const int base = b * chunks;
    const int cid  = base + k;
    if (g == 0) ((float4*)g_L)[(size_t)cid * 64 + l] = Lb;
    __syncthreads();
    if (tid == 0) {
        asm volatile("st.release.gpu.global.b32 [%0], %1;"
                     :: "l"(&g_flag[cid]), "r"(1) : "memory");
    }

    // ---- prefetch first PF rows for phase 3 (independent of the carry) ----
    float4 p3[PF];
    if (full) {
        #pragma unroll
        for (int u = 0; u < PF; ++u) p3[u] = __ldcs(zb4 + (size_t)u * strd);
    }

    // ---- phase 2a: PARALLEL wait on predecessor flags + gather end-times ----
    if (tid < k) {
        int f;
        do {
            asm volatile("ld.acquire.gpu.global.b32 %0, [%1];"
                         : "=r"(f) : "l"(&g_flag[base + tid]) : "memory");
            if (!f) __nanosleep(32);
        } while (!f);
        s_T[tid] = tb[(tid + 1) * CS - 1];
    }
    __syncthreads();

    // ---- phase 2b: block carry (closed form over predecessor chunks) ----
    float4 a0 = make_float4(0.f, 0.f, 0.f, 0.f);
    float4 a1 = make_float4(0.f, 0.f, 0.f, 0.f);
    const float4* Lp = ((const float4*)g_L) + (size_t)base * 64 + l;
    int j = 0;
    for (; j + 2 <= k; j += 2) {
        const float w0 = __expf(-THETA * (Tprev - s_T[j]));
        const float w1 = __expf(-THETA * (Tprev - s_T[j + 1]));
        fma4(a0, w0, Lp[(size_t)j * 64]);
        fma4(a1, w1, Lp[(size_t)(j + 1) * 64]);
    }
    if (j < k)
        fma4(a0, __expf(-THETA * (Tprev - s_T[j])), Lp[(size_t)j * 64]);
    float4 carry = make_float4(a0.x + a1.x, a0.y + a1.y, a0.z + a1.z, a0.w + a1.w);

    // ---- state entering THIS thread's subgroup ----
    const float Tgprev = (g == 0) ? Tprev : s_Tg[g - 1];
    float4 e = make_float4(0.f, 0.f, 0.f, 0.f);
    fma4(e, __expf(-THETA * (Tgprev - Tprev)), carry);
    for (int gp = 0; gp < g; ++gp)
        fma4(e, __expf(-THETA * (Tgprev - s_Tg[gp])), s_P[gp * 64 + l]);
    if (k == 0 && g == 0) {
        e.x += x0v.x; e.y += x0v.y; e.z += x0v.z; e.w += x0v.w;
    }

    // ---- phase 3: re-read z (L2-hot due to reversal), forward recurrence ----
    float4* ob4 = (float4*)(out + ((size_t)b * S + s0 + r0) * D) + l;
    float4 y = e;
    if (full) {
        float4 cur[PF], nxt[PF];
        #pragma unroll
        for (int u = 0; u < PF; ++u) cur[u] = p3[u];
        for (int s = 0; s < RG; s += PF) {
            if (s + 2 * PF <= RG) {
                #pragma unroll
                for (int u = 0; u < PF; ++u)
                    nxt[u] = __ldcs(zb4 + (size_t)(s + PF + u) * strd);
            }
            #pragma unroll
            for (int u = 0; u < PF; ++u) {
                const float c = s_c[r0 + s + u];
                const float r = s_r[r0 + s + u];
                y.x = fmaf(c, y.x, r * cur[u].x);
                y.y = fmaf(c, y.y, r * cur[u].y);
                y.z = fmaf(c, y.z, r * cur[u].z);
                y.w = fmaf(c, y.w, r * cur[u].w);
                __stcs(ob4 + (size_t)(s + u) * strd, y);
            }
            #pragma unroll
            for (int u = 0; u < PF; ++u) cur[u] = nxt[u];
        }
    } else {
        const int gr = max(0, min(RG, rows - r0));
        for (int s = 0; s < gr; ++s) {
            const float4 zv = __ldcs(zb4 + (size_t)s * strd);
            const float c = s_c[r0 + s], r = s_r[r0 + s];
            y.x = fmaf(c, y.x, r * zv.x);
            y.y = fmaf(c, y.y, r * zv.y);
            y.z = fmaf(c, y.z, r * zv.z);
            y.w = fmaf(c, y.w, r * zv.w);
            __stcs(ob4 + (size_t)s * strd, y);
        }
    }
}

extern "C" void kernel_launch(void* const* d_in, const int* in_sizes, int n_in,
                              void* d_out, int out_size)
{
    const float* t  = (const float*)d_in[0];   // [B,S,1]
    const float* x0 = (const float*)d_in[1];   // [B,1,D]
    const float* z  = (const float*)d_in[2];   // [B,S,D]
    float* out = (float*)d_out;                // [B,S,D]

    const long n_t  = in_sizes[0];
    const long n_x0 = in_sizes[1];
    const long n_z  = in_sizes[2];
    const int D = (int)(n_z / n_t);
    const int B = (int)(n_x0 / D);
    const int S = (int)(n_t / B);
    const int chunks = (S + CS - 1) / CS;

    const int nflags = B * chunks;
    init_flags_kernel<<<(nflags + 255) / 256, 256>>>(nflags);

    const size_t smem = SM_HDR * sizeof(float) + (size_t)(NG * 64) * sizeof(float4);
    cudaFuncSetAttribute(ou_scan_kernel,
                         cudaFuncAttributeMaxDynamicSharedMemorySize, (int)smem);
    ou_scan_kernel<<<B * chunks, 256, smem>>>(t, x0, z, out, B, S, D, chunks);
}